// round 16
// baseline (speedup 1.0000x reference)
#include <cuda_runtime.h>
#include <cuda_fp16.h>
#include <cfloat>
#include <cstdint>
#include <cstdio>

// ---------------------------------------------------------------------------
// Problem constants
// ---------------------------------------------------------------------------
static constexpr int NBATCH   = 8192;
static constexpr int DBODY    = 64;
static constexpr int DOBJ     = 128;
static constexpr int NOBJ     = 9;
static constexpr int NEDGE    = 72;
static constexpr int DEDGE    = 128;
static constexpr int NISO     = 3;
static constexpr int NNODE    = NOBJ + NISO;      // 12
static constexpr int HID      = 256;
static constexpr int PHI_OUT  = 256;
static constexpr int ACT      = 32;
static constexpr int OBS_LD   = DBODY + NOBJ * DOBJ;  // 1216
static constexpr int W1_K     = DBODY + 256;          // 320

// ---------------------------------------------------------------------------
// Scratch (device globals -- no dynamic allocation allowed)
// ---------------------------------------------------------------------------
__device__ __half g_Xnf[(size_t)NNODE * NBATCH * 256];    // packed inputs (half)
__device__ __half g_body[(size_t)NBATCH * DBODY];         // obs body (half)
__device__ float  g_Cbody[(size_t)NBATCH * HID];          // body @ W1[:64] (fp32)
__device__ __half g_H[(size_t)NNODE * NBATCH * HID];      // layer-1 acts (half)
__device__ __half g_P[(size_t)NNODE * NBATCH * PHI_OUT];  // layer-2 acts (half)
__device__ __half g_pooled[(size_t)NBATCH * PHI_OUT];     // pooled (half)
__device__ float  g_R[(size_t)NBATCH * HID];
__device__ int    g_seglist[NOBJ * NEDGE];
__device__ int    g_segcnt[NOBJ];
// half, TRANSPOSED weights [N][K] (k-contiguous) for the fp16 MMA B operand
__device__ __half g_W1T[HID * W1_K];        // [256][320]
__device__ __half g_W2T[PHI_OUT * HID];     // [256][256]
__device__ __half g_WrT[HID * PHI_OUT];     // [256][256]

// ---------------------------------------------------------------------------
// helpers
// ---------------------------------------------------------------------------
__device__ __forceinline__ void mma_f16(float (&c)[4],
                                        const uint32_t (&a)[4],
                                        const uint32_t (&b)[2]) {
    asm volatile(
        "mma.sync.aligned.m16n8k16.row.col.f32.f16.f16.f32 "
        "{%0,%1,%2,%3}, {%4,%5,%6,%7}, {%8,%9}, {%0,%1,%2,%3};\n"
        : "+f"(c[0]), "+f"(c[1]), "+f"(c[2]), "+f"(c[3])
        : "r"(a[0]), "r"(a[1]), "r"(a[2]), "r"(a[3]),
          "r"(b[0]), "r"(b[1]));
}

__device__ __forceinline__ void cp16(uint32_t saddr, const void* g) {
    asm volatile("cp.async.ca.shared.global [%0], [%1], 16;\n"
                 :: "r"(saddr), "l"(g));
}

// ---------------------------------------------------------------------------
// K-1: weights -> half, transposed to [N][K]
// ---------------------------------------------------------------------------
__global__ void prep_kernel(const float* __restrict__ W1,
                            const float* __restrict__ W2,
                            const float* __restrict__ Wr) {
    int idx = blockIdx.x * 256 + threadIdx.x;
    if (idx < HID * W1_K) {                 // W1T[n][k] = W1[k][n]
        int n = idx / W1_K, k = idx % W1_K;
        g_W1T[idx] = __float2half_rn(W1[k * HID + n]);
    }
    if (idx < PHI_OUT * HID) {
        int n = idx >> 8, k = idx & 255;
        g_W2T[idx] = __float2half_rn(W2[k * PHI_OUT + n]);
        g_WrT[idx] = __float2half_rn(Wr[k * HID + n]);
    }
}

// ---------------------------------------------------------------------------
// K-0b: obs body -> half  [B][64]
// ---------------------------------------------------------------------------
__global__ void body_kernel(const float* __restrict__ obs) {
    int idx = blockIdx.x * 256 + threadIdx.x;   // over B*64
    int b = idx >> 6, d = idx & 63;
    g_body[idx] = __float2half_rn(obs[(size_t)b * OBS_LD + d]);
}

// ---------------------------------------------------------------------------
// K0: build segment lists from edges_to (generic, honors the input array)
// ---------------------------------------------------------------------------
__global__ void seg_kernel(const int* __restrict__ edges_to) {
    if (threadIdx.x == 0 && blockIdx.x == 0) {
        for (int n = 0; n < NOBJ; ++n) {
            int c = 0;
            for (int e = 0; e < NEDGE; ++e)
                if (edges_to[e] == n) g_seglist[n * NEDGE + c++] = e;
            g_segcnt[n] = c;
        }
    }
}

// ---------------------------------------------------------------------------
// K1: segment-max + pack -> half Xnf[n*B+b] = [node(128)|feat(128)]
// ---------------------------------------------------------------------------
__global__ void pack_kernel(const float* __restrict__ obs,
                            const float* __restrict__ edges,
                            const float* __restrict__ iso,
                            const float* __restrict__ isof) {
    int n     = blockIdx.x % NNODE;
    size_t b  = blockIdx.x / NNODE;
    int d     = threadIdx.x;                       // 0..127

    float node, feat;
    if (n < NOBJ) {
        node = obs[b * OBS_LD + DBODY + (size_t)n * DOBJ + d];
        float m = -FLT_MAX;
        int cnt = g_segcnt[n];
        for (int k = 0; k < cnt; ++k) {
            int e = g_seglist[n * NEDGE + k];
            m = fmaxf(m, edges[(b * NEDGE + e) * DEDGE + d]);
        }
        feat = m;
    } else {
        int i = n - NOBJ;
        node = iso [(b * NISO + i) * DOBJ + d];
        feat = isof[(b * NISO + i) * DEDGE + d];
    }
    size_t row = (size_t)n * NBATCH + b;
    g_Xnf[row * 256 + d]       = __float2half_rn(node);
    g_Xnf[row * 256 + 128 + d] = __float2half_rn(feat);
}

// ---------------------------------------------------------------------------
// FP16 mma.sync GEMM: C[M,N] = op(A[M,K] @ BT[N,K]^T), fp32 accumulate.
// 128x128 CTA tile, KC=32, cp.async double-buffered, static smem 40 KB,
// __launch_bounds__(256,2) -> 2 CTAs/SM. 8 warps 4(m)x2(n); warp 32x64 =
// 2 m-frags x 8 n-frags of m16n8k16. K % 32 == 0, M % 128 == 0.
// smem stride 40 halves: word = 20*r + lc (mod 32) injective -> conflict-free.
// ---------------------------------------------------------------------------
static constexpr int HSTR   = 40;               // halves per smem row
static constexpr int HBUF   = 128 * HSTR;       // halves per A (or B) buffer

template<bool RELU, bool ROWADD, bool OUT_HALF>
__global__ __launch_bounds__(256, 2)
void gemm_f16(const __half* __restrict__ A, int lda,
              const __half* __restrict__ BT, int ldb,
              void* __restrict__ Cv, int ldc,
              int K,
              const float* __restrict__ bias,
              const float* __restrict__ rowadd,
              int rowmask) {
    __shared__ __half sA[2][128][HSTR];
    __shared__ __half sB[2][128][HSTR];

    const int tid  = threadIdx.x;
    const int m0   = blockIdx.y * 128;
    const int n0   = blockIdx.x * 128;
    const int wid  = tid >> 5;
    const int lane = tid & 31;
    const int wm   = wid >> 1;          // 0..3  (32-row band)
    const int wn   = wid & 1;           // 0..1  (64-col half)
    const int lr   = lane >> 2;         // 0..7
    const int lc   = lane & 3;          // 0..3

    float acc[2][8][4];
#pragma unroll
    for (int mf = 0; mf < 2; ++mf)
#pragma unroll
        for (int nf = 0; nf < 8; ++nf)
#pragma unroll
            for (int q = 0; q < 4; ++q) acc[mf][nf][q] = 0.f;

    const uint32_t sA0 = (uint32_t)__cvta_generic_to_shared(&sA[0][0][0]);
    const uint32_t sB0 = (uint32_t)__cvta_generic_to_shared(&sB[0][0][0]);
    const int nChunk = K >> 5;

    // staging: A chunk 128x32 halves (64 B/row), B chunk 128(n)x32(k) halves.
    // 512 cp16 each => 2 per thread per operand.
    auto issue = [&](int t, int buf) {
        const uint32_t sa = sA0 + (uint32_t)buf * (HBUF * 2);
        const uint32_t sb = sB0 + (uint32_t)buf * (HBUF * 2);
#pragma unroll
        for (int i = 0; i < 2; ++i) {
            int s = tid + 256 * i;
            int r = s >> 2, q = s & 3;           // row, 8-half slot
            uint32_t off = (uint32_t)((r * HSTR + q * 8) * 2);
            cp16(sa + off, A  + (size_t)(m0 + r) * lda + t * 32 + q * 8);
            cp16(sb + off, BT + (size_t)(n0 + r) * ldb + t * 32 + q * 8);
        }
        asm volatile("cp.async.commit_group;\n");
    };

    issue(0, 0);

    for (int t = 0; t < nChunk; ++t) {
        if (t + 1 < nChunk) {
            issue(t + 1, (t + 1) & 1);
            asm volatile("cp.async.wait_group 1;\n");
        } else {
            asm volatile("cp.async.wait_group 0;\n");
        }
        __syncthreads();

        const __half* bufA = &sA[t & 1][0][0];
        const __half* bufB = &sB[t & 1][0][0];

#pragma unroll
        for (int ks = 0; ks < 2; ++ks) {          // two K=16 steps per chunk
            const int k0 = ks * 16;
            uint32_t a[2][4];
#pragma unroll
            for (int mf = 0; mf < 2; ++mf) {
                const __half* p = bufA + (wm * 32 + mf * 16 + lr) * HSTR + k0 + 2 * lc;
                a[mf][0] = *(const uint32_t*)(p);
                a[mf][1] = *(const uint32_t*)(p + 8 * HSTR);
                a[mf][2] = *(const uint32_t*)(p + 8);
                a[mf][3] = *(const uint32_t*)(p + 8 * HSTR + 8);
            }
            uint32_t b[8][2];
#pragma unroll
            for (int nf = 0; nf < 8; ++nf) {
                const __half* p = bufB + (wn * 64 + nf * 8 + lr) * HSTR + k0 + 2 * lc;
                b[nf][0] = *(const uint32_t*)(p);
                b[nf][1] = *(const uint32_t*)(p + 8);
            }
#pragma unroll
            for (int mf = 0; mf < 2; ++mf)
#pragma unroll
                for (int nf = 0; nf < 8; ++nf)
                    mma_f16(acc[mf][nf], a[mf], b[nf]);
        }
        __syncthreads();
    }

    // epilogue: c0,c1 at (row, 2*lc+{0,1}); c2,c3 at (row+8, ...)
    const int r_base = m0 + wm * 32 + lr;
    const int c_base = n0 + wn * 64 + 2 * lc;
#pragma unroll
    for (int mf = 0; mf < 2; ++mf) {
#pragma unroll
        for (int half_i = 0; half_i < 2; ++half_i) {
            const int row = r_base + mf * 16 + half_i * 8;
            const float* rp = nullptr;
            if (ROWADD) rp = rowadd + ((size_t)(row & rowmask) << 8);
#pragma unroll
            for (int nf = 0; nf < 8; ++nf) {
                const int col = c_base + nf * 8;
                float v0 = acc[mf][nf][half_i * 2 + 0];
                float v1 = acc[mf][nf][half_i * 2 + 1];
                if (bias) {
                    float2 bv = *(const float2*)&bias[col];
                    v0 += bv.x; v1 += bv.y;
                }
                if (ROWADD) {
                    float2 av = *(const float2*)&rp[col];
                    v0 += av.x; v1 += av.y;
                }
                if (RELU) { v0 = fmaxf(v0, 0.f); v1 = fmaxf(v1, 0.f); }
                if (OUT_HALF) {
                    __half2* Cp = (__half2*)((__half*)Cv + (size_t)row * ldc + col);
                    *Cp = __floats2half2_rn(v0, v1);
                } else {
                    *(float2*)((float*)Cv + (size_t)row * ldc + col) = make_float2(v0, v1);
                }
            }
        }
    }
}

// ---------------------------------------------------------------------------
// K4b: pooled[b][j] = half(sum_n P[n*B+b][j]) (fp32 accumulate, deterministic)
// ---------------------------------------------------------------------------
__global__ void pool_kernel() {
    size_t idx = (size_t)blockIdx.x * blockDim.x + threadIdx.x;   // over B*256
    float s = 0.f;
#pragma unroll
    for (int n = 0; n < NNODE; ++n)
        s += __half2float(g_P[(size_t)n * NBATCH * PHI_OUT + idx]);
    g_pooled[idx] = __float2half_rn(s);
}

// ---------------------------------------------------------------------------
// K5b: mean = R@Wm+bm ; log_std = clip(R@Ws+bs). 32 batch rows per CTA.
// ---------------------------------------------------------------------------
__global__ __launch_bounds__(256)
void heads_kernel(const float* __restrict__ Wm, const float* __restrict__ bm,
                  const float* __restrict__ Ws, const float* __restrict__ bs,
                  float* __restrict__ out) {
    __shared__ float sR[32 * 256];
    const int tid = threadIdx.x;
    const size_t b0 = (size_t)blockIdx.x * 32;

    const float4* src = (const float4*)(g_R + b0 * 256);
    float4* dst = (float4*)sR;
#pragma unroll
    for (int i = 0; i < 8; ++i) dst[tid + i * 256] = src[tid + i * 256];
    __syncthreads();

    const int j  = tid & 63;
    const int rg = tid >> 6;
    const bool isMean = (j < 32);
    const int jj = j & 31;
    const float* W = isMean ? Wm : Ws;

    float acc[8];
#pragma unroll
    for (int s = 0; s < 8; ++s) acc[s] = 0.f;

#pragma unroll 4
    for (int k = 0; k < 256; ++k) {
        float w = W[k * ACT + jj];
#pragma unroll
        for (int s = 0; s < 8; ++s)
            acc[s] = fmaf(sR[(rg + s * 4) * 256 + k], w, acc[s]);
    }

#pragma unroll
    for (int s = 0; s < 8; ++s) {
        size_t row = b0 + rg + s * 4;
        if (isMean) {
            out[row * ACT + jj] = acc[s] + bm[jj];
        } else {
            float v = acc[s] + bs[jj];
            v = fminf(fmaxf(v, -20.f), 2.f);
            out[(size_t)NBATCH * ACT + row * ACT + jj] = v;
        }
    }
}

// ---------------------------------------------------------------------------
// Host launcher
// ---------------------------------------------------------------------------
extern "C" void kernel_launch(void* const* d_in, const int* in_sizes, int n_in,
                              void* d_out, int out_size) {
    const float* obs  = (const float*)d_in[0];
    const float* ef   = (const float*)d_in[1];
    const int*   eto  = (const int*)  d_in[2];
    const float* iso  = (const float*)d_in[3];
    const float* isof = (const float*)d_in[4];
    const float* W1   = (const float*)d_in[5];
    const float* b1   = (const float*)d_in[6];
    const float* W2   = (const float*)d_in[7];
    const float* b2   = (const float*)d_in[8];
    const float* Wr   = (const float*)d_in[9];
    const float* br   = (const float*)d_in[10];
    const float* Wm   = (const float*)d_in[11];
    const float* bm   = (const float*)d_in[12];
    const float* Ws   = (const float*)d_in[13];
    const float* bs   = (const float*)d_in[14];
    float* out = (float*)d_out;

    void *pXnf, *pBody, *pCbody, *pH, *pP, *pPooled, *pR, *pW1T, *pW2T, *pWrT;
    cudaGetSymbolAddress(&pXnf,    g_Xnf);
    cudaGetSymbolAddress(&pBody,   g_body);
    cudaGetSymbolAddress(&pCbody,  g_Cbody);
    cudaGetSymbolAddress(&pH,      g_H);
    cudaGetSymbolAddress(&pP,      g_P);
    cudaGetSymbolAddress(&pPooled, g_pooled);
    cudaGetSymbolAddress(&pR,      g_R);
    cudaGetSymbolAddress(&pW1T,    g_W1T);
    cudaGetSymbolAddress(&pW2T,    g_W2T);
    cudaGetSymbolAddress(&pWrT,    g_WrT);

    // K-1: weights -> half transposed
    prep_kernel<<<(HID * W1_K + 255) / 256, 256>>>(W1, W2, Wr);

    // K-0b: body -> half
    body_kernel<<<(NBATCH * DBODY) / 256, 256>>>(obs);

    // K0: segment lists
    seg_kernel<<<1, 32>>>(eto);

    // K1: pack inputs + segment max
    pack_kernel<<<NNODE * NBATCH, 128>>>(obs, ef, iso, isof);

    // K2: C_body = body @ W1[:64,:]   (M=8192, K=64) -> fp32
    gemm_f16<false, false, false><<<dim3(2, NBATCH / 128), 256>>>(
        (const __half*)pBody, DBODY, (const __half*)pW1T, W1_K,
        pCbody, HID, DBODY, nullptr, nullptr, 0);

    // K3: H = half(relu(Xnf @ W1[64:,:] + C_body[b] + b1))   (M=98304, K=256)
    gemm_f16<true, true, true><<<dim3(2, NNODE * NBATCH / 128), 256>>>(
        (const __half*)pXnf, 256, (const __half*)pW1T + DBODY, W1_K,
        pH, HID, 256, b1, (const float*)pCbody, NBATCH - 1);

    // K4a: P = half(relu(H @ W2 + b2))   (M=98304, K=256)
    gemm_f16<true, false, true><<<dim3(2, NNODE * NBATCH / 128), 256>>>(
        (const __half*)pH, HID, (const __half*)pW2T, HID,
        pP, PHI_OUT, HID, b2, nullptr, 0);

    // K4b: pooled = half(sum_n P_n)
    pool_kernel<<<(NBATCH * PHI_OUT) / 256, 256>>>();

    // K5a: R = relu(pooled @ W1_rho + b1_rho) -> fp32   (M=8192, K=256)
    gemm_f16<true, false, false><<<dim3(2, NBATCH / 128), 256>>>(
        (const __half*)pPooled, PHI_OUT, (const __half*)pWrT, PHI_OUT,
        pR, HID, PHI_OUT, br, nullptr, 0);

    // K5b: heads
    heads_kernel<<<NBATCH / 32, 256>>>(Wm, bm, Ws, bs, out);
}